// round 2
// baseline (speedup 1.0000x reference)
#include <cuda_runtime.h>

// EnhancedLesionPenaltyLoss: pred (16,1,128,128,128) fp32 -> scalar loss.
// Single fused kernel: 512 blocks (16 batches x 32 plane-strips of 4 rows),
// each block marches z 0..127 keeping prev slice values in registers
// (d-gradient free). Cross-w diff via shuffle. Last block (atomic ticket)
// performs the deterministic fixed-order final reduction + loss formula.

namespace {
constexpr int NB      = 16;
constexpr int CHUNKS  = 32;              // 32 strips of 4 rows per plane
constexpr int NBLK    = NB * CHUNKS;     // 512 blocks
constexpr int THREADS = 128;             // 1 float4 per thread per z-step
constexpr int PLANE4  = 4096;            // float4 per z-plane (128*128/4)
constexpr int NACC    = 8;               // cmin,cmax,max,sdw,sdh,sdd,s1,s2
}

__device__ float        g_part[NBLK * NACC];
__device__ unsigned int g_ticket = 0;

__global__ __launch_bounds__(THREADS)
void lesion_fused(const float* __restrict__ pred, float* __restrict__ out) {
    const int bid   = blockIdx.x;
    const int b     = bid >> 5;          // batch
    const int chunk = bid & 31;          // plane strip
    const int tid   = threadIdx.x;
    const int lane  = tid & 31;
    const int wid   = tid >> 5;

    const float4* __restrict__ p =
        reinterpret_cast<const float4*>(pred) + (long long)b * (PLANE4 * 128);
    const int  o    = chunk * 128 + tid;  // float4 index within a plane
    const int  grow = o >> 5;             // global row 0..127 (lane == col4)
    const bool do_h = (grow < 127);

    float cmin = 0.f, cmax = 0.f, mx = 0.f;
    float sdw = 0.f, sdh = 0.f, sdd = 0.f, s1 = 0.f, s2 = 0.f;
    float4 prev = make_float4(0.f, 0.f, 0.f, 0.f);

    for (int z = 0; z < 128; ++z) {
        const float4 v = p[z * PLANE4 + o];

        // w-direction: 3 intra-vector diffs + cross-vector via shuffle.
        const float nx = __shfl_down_sync(0xffffffffu, v.x, 1);
        sdw += fabsf(v.y - v.x) + fabsf(v.z - v.y) + fabsf(v.w - v.z);
        if (lane != 31) sdw += fabsf(nx - v.w);

        // h-direction: row+1 (same plane), L1/L2-resident reload.
        if (do_h) {
            const float4 h = p[z * PLANE4 + o + 32];
            sdh += fabsf(h.x - v.x) + fabsf(h.y - v.y) +
                   fabsf(h.z - v.z) + fabsf(h.w - v.w);
        }
        // d-direction: previous slice value held in registers.
        if (z > 0) {
            sdd += fabsf(v.x - prev.x) + fabsf(v.y - prev.y) +
                   fabsf(v.z - prev.z) + fabsf(v.w - prev.w);
        }
        prev = v;

        const float xs[4] = {v.x, v.y, v.z, v.w};
#pragma unroll
        for (int k = 0; k < 4; ++k) {
            const float x = xs[k];
            if (x > 0.01f) {
                cmin += 1.f;
                s1   += x;
                s2    = fmaf(x, x, s2);
            }
            if (x > 0.5f) cmax += 1.f;
            mx = fmaxf(mx, x);
        }
    }

    // ---- block reduction (4 warps) ----
    float acc[NACC] = {cmin, cmax, mx, sdw, sdh, sdd, s1, s2};
#pragma unroll
    for (int k = 0; k < NACC; ++k) {
#pragma unroll
        for (int off = 16; off; off >>= 1) {
            const float t = __shfl_xor_sync(0xffffffffu, acc[k], off);
            acc[k] = (k == 2) ? fmaxf(acc[k], t) : (acc[k] + t);
        }
    }
    __shared__ float red[4][NACC];
    __shared__ float fin[NB][NACC];
    __shared__ float lsh[NB];
    __shared__ unsigned int tick_sh;
    if (lane == 0) {
#pragma unroll
        for (int k = 0; k < NACC; ++k) red[wid][k] = acc[k];
    }
    __syncthreads();

    if (tid == 0) {
#pragma unroll
        for (int k = 0; k < NACC; ++k) {
            float r = red[0][k];
#pragma unroll
            for (int w = 1; w < 4; ++w)
                r = (k == 2) ? fmaxf(r, red[w][k]) : (r + red[w][k]);
            g_part[bid * NACC + k] = r;
        }
        __threadfence();
        tick_sh = atomicAdd(&g_ticket, 1u);
    }
    __syncthreads();
    if (tick_sh != (unsigned)(NBLK - 1)) return;

    // ---- last block: deterministic fixed-order final reduction ----
    __threadfence();  // acquire all other blocks' g_part writes

    // 128 threads = 16 batches x 8 accumulators.
    const int fb = tid >> 3;
    const int fk = tid & 7;
    {
        const float* base = &g_part[(fb * CHUNKS) * NACC + fk];
        float r = base[0];
#pragma unroll
        for (int c = 1; c < CHUNKS; ++c) {
            const float t = base[c * NACC];
            r = (fk == 2) ? fmaxf(r, t) : (r + t);
        }
        fin[fb][fk] = r;
    }
    __syncthreads();

    if (tid < NB) {
        const float cnt   = fin[tid][0];
        const float chigh = fin[tid][1];
        const float mxv   = fin[tid][2];
        const float sw    = fin[tid][3];
        const float sh    = fin[tid][4];
        const float sd    = fin[tid][5];
        const float S1    = fin[tid][6];
        const float S2    = fin[tid][7];

        const float invN   = 1.f / 2097152.f;        // 1/128^3
        const float invND3 = 1.f / 6242304.f;        // 1/(3*127*128*128)

        const float act = cnt * invN;
        float loss = fmaxf(0.005f - act, 0.f) * 15.f;

        const float high = chigh * invN;
        loss += fmaxf(high - 0.03f, 0.f) * 5.f;

        const float avg_grad = (sw + sh + sd) * invND3;
        if (mxv > 0.3f) loss += fminf(avg_grad, 1.f) * 5.f;

        const float cnt_safe = fmaxf(cnt, 1.f);
        const float m  = S1 / cnt_safe;
        const float sq = fmaxf(S2 - 2.f * m * S1 + m * m * cnt, 0.f);
        const bool gate = (act > 0.001f) && (cnt > 1.f);
        const float var = gate ? (sq / fmaxf(cnt - 1.f, 1.f)) : 1.f;
        const float rel_std = sqrtf(var) / (m + 1e-6f);
        const float pen = expf(-5.f * rel_std);
        loss += (gate ? pen : 0.f) * 7.f;

        lsh[tid] = loss;
    }
    __syncthreads();
    if (tid == 0) {
        float t = 0.f;
#pragma unroll
        for (int i = 0; i < NB; ++i) t += lsh[i];
        out[0] = t * (1.f / 16.f);
        g_ticket = 0;  // reset for next (graph-replayed) launch
    }
}

extern "C" void kernel_launch(void* const* d_in, const int* in_sizes, int n_in,
                              void* d_out, int out_size) {
    (void)in_sizes; (void)n_in; (void)out_size;
    const float* pred = (const float*)d_in[0];
    float* out = (float*)d_out;
    lesion_fused<<<NBLK, THREADS>>>(pred, out);
}

// round 3
// speedup vs baseline: 1.5667x; 1.5667x over previous
#include <cuda_runtime.h>

// EnhancedLesionPenaltyLoss: pred (16,1,128,128,128) fp32 -> scalar loss.
// Grid: 16 batches x 16 row-strips(8 rows) x 4 z-segments(32 slices)
//     = 1024 blocks x 256 threads (55 warps/SM, single wave).
// Each thread marches its z-segment keeping prev-slice value in registers
// (d-gradient needs no extra traffic beyond one seed plane per segment).
// All three gradient sums share one accumulator (equal denominators).
// Last block (atomic ticket) does the deterministic final reduction.

namespace {
constexpr int NB      = 16;
constexpr int STRIPS  = 16;              // 8-row strips per plane
constexpr int ZSEGS   = 4;               // 32 z-slices per segment
constexpr int ZLEN    = 32;
constexpr int NBLK    = NB * STRIPS * ZSEGS;   // 1024
constexpr int THREADS = 256;             // 1 float4 per thread per z-step
constexpr int PLANE4  = 4096;            // float4 per z-plane
constexpr int NACC    = 6;               // cmin,cmax,max,sds,s1,s2
}

__device__ float        g_part[NBLK * NACC];
__device__ unsigned int g_ticket = 0;

__global__ __launch_bounds__(THREADS)
void lesion_fused(const float* __restrict__ pred, float* __restrict__ out) {
    const int bid   = blockIdx.x;
    const int zseg  = bid & 3;
    const int strip = (bid >> 2) & 15;
    const int b     = bid >> 6;
    const int tid   = threadIdx.x;
    const int lane  = tid & 31;
    const int wid   = tid >> 5;

    const float4* __restrict__ p =
        reinterpret_cast<const float4*>(pred) + (long long)b * (PLANE4 * 128);
    const int  o    = strip * 256 + tid;   // float4 index within a plane
    const int  grow = o >> 5;              // global row (lane == col4)
    const bool do_h = (grow < 127);
    const int  z0   = zseg * ZLEN;

    float cmin = 0.f, cmax = 0.f, mx = 0.f;
    float sds = 0.f, s1 = 0.f, s2 = 0.f;

    // Seed prev with plane z0-1 (or z0 itself when z0==0: diff contributes 0).
    const int zp = (z0 > 0) ? (z0 - 1) : 0;
    float4 prev = p[zp * PLANE4 + o];

    const float4* pv = p + (long long)z0 * PLANE4 + o;
    const float4* ph = pv + 32;

#pragma unroll 2
    for (int i = 0; i < ZLEN; ++i) {
        const float4 v = pv[i * PLANE4];

        // w-direction: intra-vector diffs + cross-vector via shuffle.
        const float nx = __shfl_down_sync(0xffffffffu, v.x, 1);
        float g = fabsf(v.y - v.x) + fabsf(v.z - v.y) + fabsf(v.w - v.z);
        if (lane != 31) g += fabsf(nx - v.w);

        // h-direction: row+1 (mostly other threads' v -> L1/L2 hit).
        if (do_h) {
            const float4 h = ph[i * PLANE4];
            g += fabsf(h.x - v.x) + fabsf(h.y - v.y) +
                 fabsf(h.z - v.z) + fabsf(h.w - v.w);
        }
        // d-direction: prev slice held in registers.
        g += fabsf(v.x - prev.x) + fabsf(v.y - prev.y) +
             fabsf(v.z - prev.z) + fabsf(v.w - prev.w);
        prev = v;
        sds += g;

        const float xs[4] = {v.x, v.y, v.z, v.w};
#pragma unroll
        for (int k = 0; k < 4; ++k) {
            const float x = xs[k];
            if (x > 0.01f) {
                cmin += 1.f;
                s1   += x;
                s2    = fmaf(x, x, s2);
            }
            if (x > 0.5f) cmax += 1.f;
            mx = fmaxf(mx, x);
        }
    }

    // ---- block reduction (8 warps) ----
    float acc[NACC] = {cmin, cmax, mx, sds, s1, s2};
#pragma unroll
    for (int k = 0; k < NACC; ++k) {
#pragma unroll
        for (int off = 16; off; off >>= 1) {
            const float t = __shfl_xor_sync(0xffffffffu, acc[k], off);
            acc[k] = (k == 2) ? fmaxf(acc[k], t) : (acc[k] + t);
        }
    }
    __shared__ float red[8][NACC];
    __shared__ float fin[NB][NACC];
    __shared__ float lsh[NB];
    __shared__ unsigned int tick_sh;
    if (lane == 0) {
#pragma unroll
        for (int k = 0; k < NACC; ++k) red[wid][k] = acc[k];
    }
    __syncthreads();

    if (tid == 0) {
#pragma unroll
        for (int k = 0; k < NACC; ++k) {
            float r = red[0][k];
#pragma unroll
            for (int w = 1; w < 8; ++w)
                r = (k == 2) ? fmaxf(r, red[w][k]) : (r + red[w][k]);
            g_part[bid * NACC + k] = r;
        }
        __threadfence();
        tick_sh = atomicAdd(&g_ticket, 1u);
    }
    __syncthreads();
    if (tick_sh != (unsigned)(NBLK - 1)) return;

    // ---- last block: deterministic fixed-order final reduction ----
    __threadfence();  // acquire other blocks' g_part writes

    // 16 batches x 6 accumulators = 96 active threads; each sums 64 partials.
    constexpr int PER_B = STRIPS * ZSEGS;  // 64 partial blocks per batch
    if (tid < NB * NACC) {
        const int fb = tid / NACC;
        const int fk = tid % NACC;
        const float* base = &g_part[(fb * PER_B) * NACC + fk];
        float r = base[0];
#pragma unroll
        for (int c = 1; c < PER_B; ++c) {
            const float t = base[c * NACC];
            r = (fk == 2) ? fmaxf(r, t) : (r + t);
        }
        fin[fb][fk] = r;
    }
    __syncthreads();

    if (tid < NB) {
        const float cnt   = fin[tid][0];
        const float chigh = fin[tid][1];
        const float mxv   = fin[tid][2];
        const float sg    = fin[tid][3];
        const float S1    = fin[tid][4];
        const float S2    = fin[tid][5];

        const float invN   = 1.f / 2097152.f;        // 1/128^3
        const float invND3 = 1.f / 6242304.f;        // 1/(3*127*128*128)

        const float act = cnt * invN;
        float loss = fmaxf(0.005f - act, 0.f) * 15.f;

        const float high = chigh * invN;
        loss += fmaxf(high - 0.03f, 0.f) * 5.f;

        const float avg_grad = sg * invND3;
        if (mxv > 0.3f) loss += fminf(avg_grad, 1.f) * 5.f;

        const float cnt_safe = fmaxf(cnt, 1.f);
        const float m  = S1 / cnt_safe;
        const float sq = fmaxf(S2 - 2.f * m * S1 + m * m * cnt, 0.f);
        const bool gate = (act > 0.001f) && (cnt > 1.f);
        const float var = gate ? (sq / fmaxf(cnt - 1.f, 1.f)) : 1.f;
        const float rel_std = sqrtf(var) / (m + 1e-6f);
        const float pen = expf(-5.f * rel_std);
        loss += (gate ? pen : 0.f) * 7.f;

        lsh[tid] = loss;
    }
    __syncthreads();
    if (tid == 0) {
        float t = 0.f;
#pragma unroll
        for (int i = 0; i < NB; ++i) t += lsh[i];
        out[0] = t * (1.f / 16.f);
        g_ticket = 0;  // reset for next (graph-replayed) launch
    }
}

extern "C" void kernel_launch(void* const* d_in, const int* in_sizes, int n_in,
                              void* d_out, int out_size) {
    (void)in_sizes; (void)n_in; (void)out_size;
    const float* pred = (const float*)d_in[0];
    float* out = (float*)d_out;
    lesion_fused<<<NBLK, THREADS>>>(pred, out);
}

// round 4
// speedup vs baseline: 2.2835x; 1.4575x over previous
#include <cuda_runtime.h>

// EnhancedLesionPenaltyLoss: pred (16,1,128,128,128) fp32 -> scalar loss.
// Grid: 16 batches x 16 row-strips(8 rows) x 4 z-segments(32 slices)
//     = 1024 blocks x 256 threads. __launch_bounds__(256,7) caps regs at 36
//     so 7 blocks/SM co-reside -> the ENTIRE grid fits in one wave (no tail).
// Each thread marches its z-segment keeping prev-slice value in registers.
// Unroll-4 z loop for memory-level parallelism.
// Last block (atomic ticket) does the deterministic final reduction.

namespace {
constexpr int NB      = 16;
constexpr int STRIPS  = 16;              // 8-row strips per plane
constexpr int ZSEGS   = 4;               // 32 z-slices per segment
constexpr int ZLEN    = 32;
constexpr int NBLK    = NB * STRIPS * ZSEGS;   // 1024
constexpr int THREADS = 256;             // 1 float4 per thread per z-step
constexpr int PLANE4  = 4096;            // float4 per z-plane
constexpr int NACC    = 6;               // cmin,cmax,max,sds,s1,s2
}

__device__ float        g_part[NBLK * NACC];
__device__ unsigned int g_ticket = 0;

__global__ __launch_bounds__(THREADS, 7)
void lesion_fused(const float* __restrict__ pred, float* __restrict__ out) {
    const int bid   = blockIdx.x;
    const int zseg  = bid & 3;
    const int strip = (bid >> 2) & 15;
    const int b     = bid >> 6;
    const int tid   = threadIdx.x;
    const int lane  = tid & 31;
    const int wid   = tid >> 5;

    const float4* __restrict__ p =
        reinterpret_cast<const float4*>(pred) + (long long)b * (PLANE4 * 128);
    const int  o    = strip * 256 + tid;   // float4 index within a plane
    const int  grow = o >> 5;              // global row (lane == col4)
    const bool do_h = (grow < 127);
    const int  z0   = zseg * ZLEN;

    float cmin = 0.f, cmax = 0.f, mx = 0.f;
    float sds = 0.f, s1 = 0.f, s2 = 0.f;

    // Seed prev with plane z0-1 (z0==0: self-diff contributes 0).
    const int zp = (z0 > 0) ? (z0 - 1) : 0;
    float4 prev = p[zp * PLANE4 + o];

    const float4* pv = p + (long long)z0 * PLANE4 + o;
    const float4* ph = pv + 32;

#pragma unroll 4
    for (int i = 0; i < ZLEN; ++i) {
        const float4 v = pv[i * PLANE4];
        float4 h;
        if (do_h) h = ph[i * PLANE4];

        // w-direction: intra-vector diffs + cross-vector via shuffle.
        const float nx = __shfl_down_sync(0xffffffffu, v.x, 1);
        float g = fabsf(v.y - v.x) + fabsf(v.z - v.y) + fabsf(v.w - v.z);
        if (lane != 31) g += fabsf(nx - v.w);

        // h-direction: row+1 (loaded as v by a sibling warp -> L1 hit).
        if (do_h) {
            g += fabsf(h.x - v.x) + fabsf(h.y - v.y) +
                 fabsf(h.z - v.z) + fabsf(h.w - v.w);
        }
        // d-direction: prev slice held in registers.
        g += fabsf(v.x - prev.x) + fabsf(v.y - prev.y) +
             fabsf(v.z - prev.z) + fabsf(v.w - prev.w);
        prev = v;
        sds += g;

        const float xs[4] = {v.x, v.y, v.z, v.w};
#pragma unroll
        for (int k = 0; k < 4; ++k) {
            const float x = xs[k];
            if (x > 0.01f) {
                cmin += 1.f;
                s1   += x;
                s2    = fmaf(x, x, s2);
            }
            if (x > 0.5f) cmax += 1.f;
            mx = fmaxf(mx, x);
        }
    }

    // ---- block reduction (8 warps) ----
    float acc[NACC] = {cmin, cmax, mx, sds, s1, s2};
#pragma unroll
    for (int k = 0; k < NACC; ++k) {
#pragma unroll
        for (int off = 16; off; off >>= 1) {
            const float t = __shfl_xor_sync(0xffffffffu, acc[k], off);
            acc[k] = (k == 2) ? fmaxf(acc[k], t) : (acc[k] + t);
        }
    }
    __shared__ float red[8][NACC];
    __shared__ float fin[NB][NACC];
    __shared__ float lsh[NB];
    __shared__ unsigned int tick_sh;
    if (lane == 0) {
#pragma unroll
        for (int k = 0; k < NACC; ++k) red[wid][k] = acc[k];
    }
    __syncthreads();

    if (tid == 0) {
#pragma unroll
        for (int k = 0; k < NACC; ++k) {
            float r = red[0][k];
#pragma unroll
            for (int w = 1; w < 8; ++w)
                r = (k == 2) ? fmaxf(r, red[w][k]) : (r + red[w][k]);
            g_part[bid * NACC + k] = r;
        }
        __threadfence();
        tick_sh = atomicAdd(&g_ticket, 1u);
    }
    __syncthreads();
    if (tick_sh != (unsigned)(NBLK - 1)) return;

    // ---- last block: deterministic fixed-order final reduction ----
    __threadfence();  // acquire other blocks' g_part writes

    // 16 batches x 6 accumulators = 96 active threads; each sums 64 partials.
    constexpr int PER_B = STRIPS * ZSEGS;  // 64 partial blocks per batch
    if (tid < NB * NACC) {
        const int fb = tid / NACC;
        const int fk = tid % NACC;
        const float* base = &g_part[(fb * PER_B) * NACC + fk];
        float r = base[0];
#pragma unroll
        for (int c = 1; c < PER_B; ++c) {
            const float t = base[c * NACC];
            r = (fk == 2) ? fmaxf(r, t) : (r + t);
        }
        fin[fb][fk] = r;
    }
    __syncthreads();

    if (tid < NB) {
        const float cnt   = fin[tid][0];
        const float chigh = fin[tid][1];
        const float mxv   = fin[tid][2];
        const float sg    = fin[tid][3];
        const float S1    = fin[tid][4];
        const float S2    = fin[tid][5];

        const float invN   = 1.f / 2097152.f;        // 1/128^3
        const float invND3 = 1.f / 6242304.f;        // 1/(3*127*128*128)

        const float act = cnt * invN;
        float loss = fmaxf(0.005f - act, 0.f) * 15.f;

        const float high = chigh * invN;
        loss += fmaxf(high - 0.03f, 0.f) * 5.f;

        const float avg_grad = sg * invND3;
        if (mxv > 0.3f) loss += fminf(avg_grad, 1.f) * 5.f;

        const float cnt_safe = fmaxf(cnt, 1.f);
        const float m  = S1 / cnt_safe;
        const float sq = fmaxf(S2 - 2.f * m * S1 + m * m * cnt, 0.f);
        const bool gate = (act > 0.001f) && (cnt > 1.f);
        const float var = gate ? (sq / fmaxf(cnt - 1.f, 1.f)) : 1.f;
        const float rel_std = sqrtf(var) / (m + 1e-6f);
        const float pen = expf(-5.f * rel_std);
        loss += (gate ? pen : 0.f) * 7.f;

        lsh[tid] = loss;
    }
    __syncthreads();
    if (tid == 0) {
        float t = 0.f;
#pragma unroll
        for (int i = 0; i < NB; ++i) t += lsh[i];
        out[0] = t * (1.f / 16.f);
        g_ticket = 0;  // reset for next (graph-replayed) launch
    }
}

extern "C" void kernel_launch(void* const* d_in, const int* in_sizes, int n_in,
                              void* d_out, int out_size) {
    (void)in_sizes; (void)n_in; (void)out_size;
    const float* pred = (const float*)d_in[0];
    float* out = (float*)d_out;
    lesion_fused<<<NBLK, THREADS>>>(pred, out);
}